// round 6
// baseline (speedup 1.0000x reference)
#include <cuda_runtime.h>
#include <cuda_bf16.h>
#include <cstdint>

// ---------------------------------------------------------------------------
// Multi-scale residual VQ (VectorQuantizer2): B=64, C=32, H=W=16, vocab=4096
// scales pn = {1,2,3,4,5,6,8,10,13,16}
//
// Strategy: one 2-CTA cluster per batch image. Rows of each scale's argmin are
// split between the CTA pair; idx exchanged via a __device__ array guarded by
// barrier.cluster. Codebook staged through shared memory in 512-code chunks
// (transposed float4-channel layout) so the hot loop is LDS.128 + FFMA.
// All float arithmetic uses explicit _rn intrinsics / fmaf to reproduce the
// reference's (XLA-CPU) rounding chain, because argmin tie-breaks are
// sensitive to last-ulp differences.
// ---------------------------------------------------------------------------

#define NSCALES 10
__device__ __constant__ int c_pns[NSCALES] = {1, 2, 3, 4, 5, 6, 8, 10, 13, 16};

// device scratch (static globals -- no allocation)
__device__ float4 g_et4[8 * 4096];   // [cb][code] : emb[code][4cb..4cb+3]
__device__ float  g_esq[4096];       // ||e||^2 per code (rounded squares, seq sum)
__device__ int    g_idx[64 * 256];   // per-batch argmin indices for current scale

// ---------------- shared memory ----------------
struct SMem {
    float4 ech4[8 * 512];    // 64 KB  codebook chunk, [cb][j]
    float  frest[8192];      // [h][w][c]
    float  fhat[8192];       // [h][w][c]
    float  zbuf[8192];       // z rows [r][32]; reused as gathered-code buffer
    float  tmp[6656];        // pool / upsample intermediate
    float  esq_s[512];       // chunk esq
    float  wu[256];          // upsample weights [k_in * 16 + i_out]
    float  zsq[256];         // per-row ||z||^2
};
// sizeof = 65536 + 4*(8192*3 + 6656 + 512 + 256 + 256) = 193792 bytes

__device__ __forceinline__ void cluster_sync_() {
    asm volatile("barrier.cluster.arrive.aligned;\n\t"
                 "barrier.cluster.wait.aligned;\n" ::: "memory");
}

// jax _fill_keys_cubic_kernel (a = -0.5), each op rounded separately
__device__ __forceinline__ float keys_w(float x) {
    float w;
    if (x < 1.0f) {
        float t = __fmul_rn(1.5f, x);
        t = __fsub_rn(t, 2.5f);
        t = __fmul_rn(t, x);
        t = __fmul_rn(t, x);
        w = __fadd_rn(t, 1.0f);
    } else if (x < 2.0f) {
        float t = __fmul_rn(-0.5f, x);
        t = __fadd_rn(t, 2.5f);
        t = __fmul_rn(t, x);
        t = __fsub_rn(t, 4.0f);
        t = __fmul_rn(t, x);
        w = __fadd_rn(t, 2.0f);
    } else {
        w = 0.0f;
    }
    return w;
}

// ---------------------------------------------------------------------------
// prep: transpose codebook into [cb][code] float4 layout + esq
// ---------------------------------------------------------------------------
__global__ void vq_prep_kernel(const float* __restrict__ emb) {
    int j = blockIdx.x * blockDim.x + threadIdx.x;
    if (j >= 4096) return;
    const float4* row = reinterpret_cast<const float4*>(emb + j * 32);
    float4 v[8];
#pragma unroll
    for (int cb = 0; cb < 8; cb++) v[cb] = row[cb];
    float acc = 0.0f;
#pragma unroll
    for (int cb = 0; cb < 8; cb++) {
        acc = __fadd_rn(acc, __fmul_rn(v[cb].x, v[cb].x));
        acc = __fadd_rn(acc, __fmul_rn(v[cb].y, v[cb].y));
        acc = __fadd_rn(acc, __fmul_rn(v[cb].z, v[cb].z));
        acc = __fadd_rn(acc, __fmul_rn(v[cb].w, v[cb].w));
    }
    g_esq[j] = acc;
#pragma unroll
    for (int cb = 0; cb < 8; cb++) g_et4[cb * 4096 + j] = v[cb];
}

// ---------------------------------------------------------------------------
// distance pass: 8 warps x R rows, full 4096-code scan via smem chunks
// ---------------------------------------------------------------------------
template <int R>
__device__ void dist_pass(SMem* sm, int base, int rhi, int tid, int b) {
    const int lane = tid & 31;
    const int wid = tid >> 5;
    const int r0 = base + wid * R;

    float zn[R][32];
    float zs[R];
#pragma unroll
    for (int r = 0; r < R; r++) {
        int row = r0 + r;
        if (row > rhi - 1) row = rhi - 1;
        zs[r] = sm->zsq[row];
#pragma unroll
        for (int c = 0; c < 32; c++)
            zn[r][c] = __fmul_rn(-2.0f, sm->zbuf[row * 32 + c]);  // exact *(-2)
    }

    float best[R];
    int bidx[R];
#pragma unroll
    for (int r = 0; r < R; r++) { best[r] = __int_as_float(0x7f800000); bidx[r] = 0; }

    for (int chunk = 0; chunk < 4096; chunk += 512) {
        __syncthreads();
        for (int t = tid; t < 4096; t += 256)
            sm->ech4[t] = g_et4[(t >> 9) * 4096 + chunk + (t & 511)];
        for (int t = tid; t < 512; t += 256)
            sm->esq_s[t] = g_esq[chunk + t];
        __syncthreads();

#pragma unroll 2
        for (int k = 0; k < 16; k++) {
            const int j = lane + k * 32;
            float acc[R];
#pragma unroll
            for (int r = 0; r < R; r++) acc[r] = 0.0f;
#pragma unroll
            for (int cb = 0; cb < 8; cb++) {
                float4 e = sm->ech4[cb * 512 + j];
#pragma unroll
                for (int r = 0; r < R; r++) {
                    acc[r] = fmaf(zn[r][cb * 4 + 0], e.x, acc[r]);
                    acc[r] = fmaf(zn[r][cb * 4 + 1], e.y, acc[r]);
                    acc[r] = fmaf(zn[r][cb * 4 + 2], e.z, acc[r]);
                    acc[r] = fmaf(zn[r][cb * 4 + 3], e.w, acc[r]);
                }
            }
            const float eq = sm->esq_s[j];
            const int jd = chunk + j;
#pragma unroll
            for (int r = 0; r < R; r++) {
                // d = (zsq + esq) - 2*dot, with acc == -2*dot bitwise
                float d = __fadd_rn(__fadd_rn(zs[r], eq), acc[r]);
                if (d < best[r]) { best[r] = d; bidx[r] = jd; }
            }
        }
    }

    // warp-level argmin reduce; ties -> smallest index (matches jnp.argmin)
#pragma unroll
    for (int r = 0; r < R; r++) {
        unsigned ub = __float_as_uint(best[r]);
        ub = (ub & 0x80000000u) ? ~ub : (ub ^ 0x80000000u);
        unsigned long long key = ((unsigned long long)ub << 32) | (unsigned)bidx[r];
#pragma unroll
        for (int m = 16; m; m >>= 1) {
            unsigned long long o = __shfl_xor_sync(0xffffffffu, key, m);
            if (o < key) key = o;
        }
        int row = r0 + r;
        if (lane == 0 && row < rhi)
            g_idx[b * 256 + row] = (int)(key & 0xffffffffu);
    }
}

// ---------------------------------------------------------------------------
// main kernel: one cluster (2 CTAs) per batch image
// ---------------------------------------------------------------------------
extern "C" __global__ void __cluster_dims__(2, 1, 1) __launch_bounds__(256, 1)
vq_main_kernel(const float* __restrict__ f, const float* __restrict__ emb,
               float* __restrict__ out) {
    extern __shared__ char smem_raw[];
    SMem* sm = reinterpret_cast<SMem*>(smem_raw);

    const int tid = threadIdx.x;
    const int b = blockIdx.x >> 1;
    const int rank = blockIdx.x & 1;

    // init: frest = transpose(f) (BCHW -> HWC), fhat = 0
    for (int t = tid; t < 8192; t += 256) {
        int c = t & 31;
        int ij = t >> 5;
        sm->frest[t] = f[(b * 32 + c) * 256 + ij];
        sm->fhat[t] = 0.0f;
    }
    __syncthreads();

    for (int si = 0; si < NSCALES; si++) {
        const int pn = c_pns[si];
        const int N = pn * pn;
        const bool last = (si == NSCALES - 1);

        // ---------- z = area pool of frest (or copy, last scale) ----------
        if (last) {
            for (int t = tid; t < 8192; t += 256) sm->zbuf[t] = sm->frest[t];
        } else {
            // pass 1: contract h (ascending, fma chain from 0)
            const int n1 = pn * 16 * 32;
            for (int t = tid; t < n1; t += 256) {
                int c = t & 31, w = (t >> 5) & 15, p = t >> 9;
                int sh = (p * 16) / pn;
                int eh = ((p + 1) * 16 + pn - 1) / pn;
                float wt = (float)(1.0 / (double)(eh - sh));
                float acc = 0.0f;
                for (int h = sh; h < eh; h++)
                    acc = fmaf(wt, sm->frest[(h * 16 + w) * 32 + c], acc);
                sm->tmp[t] = acc;
            }
            __syncthreads();
            // pass 2: contract w
            const int n2 = N * 32;
            for (int t = tid; t < n2; t += 256) {
                int c = t & 31, q = (t >> 5) % pn, p = (t >> 5) / pn;
                int sw = (q * 16) / pn;
                int ew = ((q + 1) * 16 + pn - 1) / pn;
                float wt = (float)(1.0 / (double)(ew - sw));
                float acc = 0.0f;
                for (int w = sw; w < ew; w++)
                    acc = fmaf(wt, sm->tmp[p * 512 + w * 32 + c], acc);
                sm->zbuf[t] = acc;
            }
        }
        __syncthreads();

        // ---------- zsq (rounded squares, sequential ascending sum) ----------
        if (tid < N) {
            float acc = 0.0f;
            for (int c = 0; c < 32; c++) {
                float z = sm->zbuf[tid * 32 + c];
                acc = __fadd_rn(acc, __fmul_rn(z, z));
            }
            sm->zsq[tid] = acc;
        }
        __syncthreads();

        // ---------- distance + argmin over my half of the rows ----------
        const int rlo = rank ? (N + 1) / 2 : 0;
        const int rhi = rank ? N : (N + 1) / 2;
        const int myrows = rhi - rlo;
        int R = (myrows + 7) / 8;
        if (R > 4) R = 4;
        if (R == 4) {
            for (int base = rlo; base < rhi; base += 32) dist_pass<4>(sm, base, rhi, tid, b);
        } else if (R == 3) {
            for (int base = rlo; base < rhi; base += 24) dist_pass<3>(sm, base, rhi, tid, b);
        } else if (R == 2) {
            for (int base = rlo; base < rhi; base += 16) dist_pass<2>(sm, base, rhi, tid, b);
        } else if (R == 1) {
            for (int base = rlo; base < rhi; base += 8) dist_pass<1>(sm, base, rhi, tid, b);
        }

        // ---------- exchange idx between the CTA pair ----------
        cluster_sync_();   // all g_idx writes for this scale now visible

        // ---------- gather h = emb[idx]  (overwrites zbuf) ----------
        for (int t = tid; t < N * 32; t += 256)
            sm->zbuf[t] = emb[g_idx[b * 256 + (t >> 5)] * 32 + (t & 31)];
        __syncthreads();

        // ---------- upsample (bicubic, jax semantics) + update ----------
        if (last) {
            for (int t = tid; t < 8192; t += 256)
                sm->fhat[t] = __fadd_rn(sm->fhat[t], sm->zbuf[t]);
        } else {
            // weights: compute_weight_mat(pn, 16, 16/pn, 0, keys_cubic, True)
            if (tid < 16) {
                const int i = tid;
                double scl_d = 16.0 / (double)pn;          // python float scale
                float inv = (float)(1.0 / scl_d);          // f64 recip -> f32
                float sf = __fsub_rn(__fmul_rn(__fadd_rn((float)i, 0.5f), inv), 0.5f);
                float tot = 0.0f;
                for (int k = 0; k < pn; k++) {
                    float x = fabsf(__fsub_rn(sf, (float)k));
                    tot = __fadd_rn(tot, keys_w(x));
                }
                for (int k = 0; k < pn; k++) {
                    float x = fabsf(__fsub_rn(sf, (float)k));
                    sm->wu[k * 16 + i] = __fdiv_rn(keys_w(x), tot);
                }
            }
            __syncthreads();
            // pass 1: contract input-h (k ascending)
            const int n1 = 16 * pn * 32;
            for (int t = tid; t < n1; t += 256) {
                int c = t & 31, kw = (t >> 5) % pn, i = (t >> 5) / pn;
                float acc = 0.0f;
                for (int k = 0; k < pn; k++)
                    acc = fmaf(sm->wu[k * 16 + i], sm->zbuf[(k * pn + kw) * 32 + c], acc);
                sm->tmp[t] = acc;   // layout (i*pn + kw)*32 + c
            }
            __syncthreads();
            // pass 2: contract input-w, then update fhat/frest
            for (int t = tid; t < 8192; t += 256) {
                int c = t & 31, j = (t >> 5) & 15, i = t >> 9;
                float acc = 0.0f;
                for (int k = 0; k < pn; k++)
                    acc = fmaf(sm->wu[k * 16 + j], sm->tmp[(i * pn + k) * 32 + c], acc);
                sm->fhat[t] = __fadd_rn(sm->fhat[t], acc);
                sm->frest[t] = __fsub_rn(sm->frest[t], acc);
            }
        }

        cluster_sync_();   // peer done reading g_idx; frest/fhat settled
    }

    // ---------- write output: BHWC -> BCHW, split channels by rank ----------
    for (int t = tid; t < 4096; t += 256) {
        int c = rank * 16 + (t >> 8);
        int ij = t & 255;
        out[(b * 32 + c) * 256 + ij] = sm->fhat[ij * 32 + c];
    }
}

// ---------------------------------------------------------------------------
extern "C" void kernel_launch(void* const* d_in, const int* in_sizes, int n_in,
                              void* d_out, int out_size) {
    (void)in_sizes; (void)n_in; (void)out_size;
    const float* f = (const float*)d_in[0];     // [64,32,16,16] f32
    const float* emb = (const float*)d_in[1];   // [4096,32] f32
    float* out = (float*)d_out;                 // [64,32,16,16] f32

    static int smem_set = 0;
    if (!smem_set) {
        cudaFuncSetAttribute(vq_main_kernel,
                             cudaFuncAttributeMaxDynamicSharedMemorySize,
                             (int)sizeof(SMem));
        smem_set = 1;
    }

    vq_prep_kernel<<<16, 256>>>(emb);
    vq_main_kernel<<<128, 256, sizeof(SMem)>>>(f, emb, out);
}

// round 7
// speedup vs baseline: 1.2774x; 1.2774x over previous
#include <cuda_runtime.h>
#include <cuda_bf16.h>
#include <cstdint>

// ---------------------------------------------------------------------------
// Multi-scale residual VQ (VectorQuantizer2): B=64, C=32, H=W=16, vocab=4096
// scales pn = {1,2,3,4,5,6,8,10,13,16}
//
// One 2-CTA cluster per batch image. The 4096-entry codebook is split between
// the CTA pair (2048 codes each); every CTA evaluates ALL rows of each scale
// against its half, then the pair merges per-row (dist,idx) keys via a global
// scratch + barrier.cluster. The hot loop packs TWO rows per accumulator with
// fma.rn.f32x2 (each half rounds exactly like scalar fmaf -> bit-identical to
// the reference's sequential FMA chain), doubling fp32 FMA throughput.
// Codebook chunks (1024 codes, 128 KB) are staged to smem once per scale.
// ---------------------------------------------------------------------------

#define NSCALES 10
__device__ __constant__ int c_pns[NSCALES] = {1, 2, 3, 4, 5, 6, 8, 10, 13, 16};

// device scratch (static globals -- no allocation)
__device__ float4 g_et4[8 * 4096];               // [cb][code] : emb[code][4cb..4cb+3]
__device__ float  g_esq[4096];                   // ||e||^2 (rounded squares, seq sum)
__device__ unsigned long long g_key[64 * 512];   // per-batch, per-rank best keys

// ---------------- shared memory ----------------
struct SMem {
    float4 ech[8 * 1024];        // 128 KB codebook chunk [cb][j]; aliased as tmp scratch
    float  esq_s[1024];          // 4 KB chunk esq
    float  frest[8192];          // [h][w][c]
    float  fhat[8192];           // [h][w][c]
    float  zbuf[176 * 32];       // z rows / gathered codes (N<=169 for non-last scales)
    float  zsq[256];             // per-row ||z||^2
    float  wu[256];              // upsample weights [k_in*16 + i_out]
    unsigned long long bkey[256];// running best (dist,idx) key per row
    int    idxs[256];            // merged final indices
};

__device__ __forceinline__ void cluster_sync_() {
    asm volatile("barrier.cluster.arrive.aligned;\n\t"
                 "barrier.cluster.wait.aligned;\n" ::: "memory");
}

__device__ __forceinline__ void ffma2(unsigned long long& acc,
                                      unsigned long long a, unsigned long long b) {
    asm("fma.rn.f32x2 %0, %1, %2, %0;" : "+l"(acc) : "l"(a), "l"(b));
}
__device__ __forceinline__ unsigned long long dup2(float v) {
    unsigned long long d;
    unsigned u = __float_as_uint(v);
    asm("mov.b64 %0, {%1, %1};" : "=l"(d) : "r"(u));
    return d;
}
__device__ __forceinline__ unsigned long long pack2(float lo, float hi) {
    unsigned long long d;
    unsigned a = __float_as_uint(lo), b = __float_as_uint(hi);
    asm("mov.b64 %0, {%1, %2};" : "=l"(d) : "r"(a), "r"(b));
    return d;
}

// jax _fill_keys_cubic_kernel (a = -0.5), each op rounded separately
__device__ __forceinline__ float keys_w(float x) {
    float w;
    if (x < 1.0f) {
        float t = __fmul_rn(1.5f, x);
        t = __fsub_rn(t, 2.5f);
        t = __fmul_rn(t, x);
        t = __fmul_rn(t, x);
        w = __fadd_rn(t, 1.0f);
    } else if (x < 2.0f) {
        float t = __fmul_rn(-0.5f, x);
        t = __fadd_rn(t, 2.5f);
        t = __fmul_rn(t, x);
        t = __fsub_rn(t, 4.0f);
        t = __fmul_rn(t, x);
        w = __fadd_rn(t, 2.0f);
    } else {
        w = 0.0f;
    }
    return w;
}

// ---------------------------------------------------------------------------
// prep: transpose codebook into [cb][code] float4 layout + esq
// ---------------------------------------------------------------------------
__global__ void vq_prep_kernel(const float* __restrict__ emb) {
    int j = blockIdx.x * blockDim.x + threadIdx.x;
    if (j >= 4096) return;
    const float4* row = reinterpret_cast<const float4*>(emb + j * 32);
    float4 v[8];
#pragma unroll
    for (int cb = 0; cb < 8; cb++) v[cb] = row[cb];
    float acc = 0.0f;
#pragma unroll
    for (int cb = 0; cb < 8; cb++) {
        acc = __fadd_rn(acc, __fmul_rn(v[cb].x, v[cb].x));
        acc = __fadd_rn(acc, __fmul_rn(v[cb].y, v[cb].y));
        acc = __fadd_rn(acc, __fmul_rn(v[cb].z, v[cb].z));
        acc = __fadd_rn(acc, __fmul_rn(v[cb].w, v[cb].w));
    }
    g_esq[j] = acc;
#pragma unroll
    for (int cb = 0; cb < 8; cb++) g_et4[cb * 4096 + j] = v[cb];
}

// ---------------------------------------------------------------------------
// main kernel: one cluster (2 CTAs) per batch image
// ---------------------------------------------------------------------------
extern "C" __global__ void __cluster_dims__(2, 1, 1) __launch_bounds__(256, 1)
vq_main_kernel(const float* __restrict__ f, const float* __restrict__ emb,
               float* __restrict__ out) {
    extern __shared__ char smem_raw[];
    SMem* sm = reinterpret_cast<SMem*>(smem_raw);

    const int tid = threadIdx.x;
    const int lane = tid & 31;
    const int wid = tid >> 5;
    const int b = blockIdx.x >> 1;
    const int rank = blockIdx.x & 1;

    // init: frest = transpose(f) (BCHW -> HWC), fhat = 0
    for (int t = tid; t < 8192; t += 256) {
        int c = t & 31;
        int ij = t >> 5;
        sm->frest[t] = f[(b * 32 + c) * 256 + ij];
        sm->fhat[t] = 0.0f;
    }
    __syncthreads();

    float* tmpf = reinterpret_cast<float*>(sm->ech);   // scratch alias

    for (int si = 0; si < NSCALES; si++) {
        const int pn = c_pns[si];
        const int N = pn * pn;
        const bool last = (si == NSCALES - 1);

        // ---------- z = area pool of frest (last scale: z aliases frest) ----------
        if (!last) {
            // pass 1: contract h (ascending, fma chain from 0) -> tmpf
            const int n1 = pn * 16 * 32;
            for (int t = tid; t < n1; t += 256) {
                int c = t & 31, w = (t >> 5) & 15, p = t >> 9;
                int sh = (p * 16) / pn;
                int eh = ((p + 1) * 16 + pn - 1) / pn;
                float wt = (float)(1.0 / (double)(eh - sh));
                float acc = 0.0f;
                for (int h = sh; h < eh; h++)
                    acc = fmaf(wt, sm->frest[(h * 16 + w) * 32 + c], acc);
                tmpf[t] = acc;
            }
            __syncthreads();
            // pass 2: contract w -> zbuf
            const int n2 = N * 32;
            for (int t = tid; t < n2; t += 256) {
                int c = t & 31, q = (t >> 5) % pn, p = (t >> 5) / pn;
                int sw = (q * 16) / pn;
                int ew = ((q + 1) * 16 + pn - 1) / pn;
                float wt = (float)(1.0 / (double)(ew - sw));
                float acc = 0.0f;
                for (int w = sw; w < ew; w++)
                    acc = fmaf(wt, tmpf[p * 512 + w * 32 + c], acc);
                sm->zbuf[t] = acc;
            }
            __syncthreads();
        }
        const float* zp = last ? sm->frest : sm->zbuf;

        // ---------- zsq (rounded squares, sequential ascending sum) ----------
        if (tid < N) {
            float acc = 0.0f;
            for (int c = 0; c < 32; c++) {
                float z = zp[tid * 32 + c];
                acc = __fadd_rn(acc, __fmul_rn(z, z));
            }
            sm->zsq[tid] = acc;
        }
        // init running best keys
        for (int t = tid; t < N; t += 256) sm->bkey[t] = 0xFFFFFFFFFFFFFFFFull;
        __syncthreads();

        // ---------- distance + argmin over this CTA's 2048-code half ----------
        const int ntiles = (N + 31) >> 5;
        for (int chunk = 0; chunk < 2; chunk++) {
            const int cbase = rank * 2048 + chunk * 1024;
            // stage 1024 codes (128 KB) + their esq
            for (int t = tid; t < 8192; t += 256)
                sm->ech[t] = g_et4[((t >> 10) << 12) + cbase + (t & 1023)];
            for (int t = tid; t < 1024; t += 256)
                sm->esq_s[t] = g_esq[cbase + t];
            __syncthreads();

            for (int tile = 0; tile < ntiles; tile++) {
                const int r0 = tile * 32 + wid * 4;
                if (r0 >= N) continue;
                int rr[4];
#pragma unroll
                for (int r = 0; r < 4; r++) {
                    int q = r0 + r;
                    rr[r] = q < N ? q : N - 1;
                }
                // pack -2*z rows: pair0 = rows(rr0,rr1), pair1 = rows(rr2,rr3)
                unsigned long long zn2[2][32];
                float zs[4];
#pragma unroll
                for (int r = 0; r < 4; r++) zs[r] = sm->zsq[rr[r]];
#pragma unroll
                for (int p = 0; p < 2; p++) {
                    const float* za = zp + rr[2 * p] * 32;
                    const float* zb = zp + rr[2 * p + 1] * 32;
#pragma unroll
                    for (int c = 0; c < 32; c++) {
                        float lo = __fmul_rn(-2.0f, za[c]);   // exact *(-2)
                        float hi = __fmul_rn(-2.0f, zb[c]);
                        zn2[p][c] = pack2(lo, hi);
                    }
                }

                float best[4];
                int bidx[4];
#pragma unroll
                for (int r = 0; r < 4; r++) {
                    best[r] = __int_as_float(0x7f800000);
                    bidx[r] = 0;
                }

#pragma unroll 1
                for (int k = 0; k < 32; k++) {
                    const int j = (k << 5) + lane;
                    unsigned long long acc0 = 0ull, acc1 = 0ull;  // {0.f,0.f}
#pragma unroll
                    for (int cb = 0; cb < 8; cb++) {
                        float4 e = sm->ech[(cb << 10) + j];
                        unsigned long long dx = dup2(e.x);
                        unsigned long long dy = dup2(e.y);
                        unsigned long long dz = dup2(e.z);
                        unsigned long long dw = dup2(e.w);
                        ffma2(acc0, zn2[0][cb * 4 + 0], dx);
                        ffma2(acc1, zn2[1][cb * 4 + 0], dx);
                        ffma2(acc0, zn2[0][cb * 4 + 1], dy);
                        ffma2(acc1, zn2[1][cb * 4 + 1], dy);
                        ffma2(acc0, zn2[0][cb * 4 + 2], dz);
                        ffma2(acc1, zn2[1][cb * 4 + 2], dz);
                        ffma2(acc0, zn2[0][cb * 4 + 3], dw);
                        ffma2(acc1, zn2[1][cb * 4 + 3], dw);
                    }
                    const float eq = sm->esq_s[j];
                    unsigned a0, a1, a2, a3;
                    asm("mov.b64 {%0, %1}, %2;" : "=r"(a0), "=r"(a1) : "l"(acc0));
                    asm("mov.b64 {%0, %1}, %2;" : "=r"(a2), "=r"(a3) : "l"(acc1));
                    const int jj = cbase + j;
                    float d0 = __fadd_rn(__fadd_rn(zs[0], eq), __uint_as_float(a0));
                    float d1 = __fadd_rn(__fadd_rn(zs[1], eq), __uint_as_float(a1));
                    float d2 = __fadd_rn(__fadd_rn(zs[2], eq), __uint_as_float(a2));
                    float d3 = __fadd_rn(__fadd_rn(zs[3], eq), __uint_as_float(a3));
                    if (d0 < best[0]) { best[0] = d0; bidx[0] = jj; }
                    if (d1 < best[1]) { best[1] = d1; bidx[1] = jj; }
                    if (d2 < best[2]) { best[2] = d2; bidx[2] = jj; }
                    if (d3 < best[3]) { best[3] = d3; bidx[3] = jj; }
                }

                // warp argmin reduce; ties -> smallest index (matches jnp.argmin)
#pragma unroll
                for (int r = 0; r < 4; r++) {
                    unsigned ub = __float_as_uint(best[r]);
                    ub = (ub & 0x80000000u) ? ~ub : (ub ^ 0x80000000u);
                    unsigned long long key =
                        ((unsigned long long)ub << 32) | (unsigned)bidx[r];
#pragma unroll
                    for (int m = 16; m; m >>= 1) {
                        unsigned long long o = __shfl_xor_sync(0xffffffffu, key, m);
                        if (o < key) key = o;
                    }
                    int row = r0 + r;
                    if (lane == 0 && row < N) {
                        unsigned long long cur = sm->bkey[row];
                        sm->bkey[row] = key < cur ? key : cur;  // owner-only RMW
                    }
                }
            }
            __syncthreads();   // chunk done before restage
        }

        // ---------- merge halves across the CTA pair ----------
        for (int t = tid; t < N; t += 256)
            g_key[(b << 9) + (rank << 8) + t] = sm->bkey[t];
        cluster_sync_();   // release/acquire covers gmem at cluster scope
        for (int t = tid; t < N; t += 256) {
            unsigned long long k0 = g_key[(b << 9) + t];
            unsigned long long k1 = g_key[(b << 9) + 256 + t];
            sm->idxs[t] = (int)((k0 < k1 ? k0 : k1) & 0xFFFFFFFFu);
        }
        __syncthreads();

        // ---------- gather h = emb[idx], upsample, update ----------
        if (last) {
            for (int t = tid; t < 8192; t += 256)
                sm->fhat[t] = __fadd_rn(sm->fhat[t],
                                        emb[sm->idxs[t >> 5] * 32 + (t & 31)]);
        } else {
            for (int t = tid; t < N * 32; t += 256)
                sm->zbuf[t] = emb[sm->idxs[t >> 5] * 32 + (t & 31)];
            // weights: compute_weight_mat(pn, 16, 16/pn, 0, keys_cubic, True)
            if (tid < 16) {
                const int i = tid;
                double scl_d = 16.0 / (double)pn;
                float inv = (float)(1.0 / scl_d);
                float sf = __fsub_rn(__fmul_rn(__fadd_rn((float)i, 0.5f), inv), 0.5f);
                float tot = 0.0f;
                for (int k = 0; k < pn; k++) {
                    float x = fabsf(__fsub_rn(sf, (float)k));
                    tot = __fadd_rn(tot, keys_w(x));
                }
                for (int k = 0; k < pn; k++) {
                    float x = fabsf(__fsub_rn(sf, (float)k));
                    sm->wu[k * 16 + i] = __fdiv_rn(keys_w(x), tot);
                }
            }
            __syncthreads();
            // pass 1: contract input-h (k ascending) -> tmpf
            const int n1 = 16 * pn * 32;
            for (int t = tid; t < n1; t += 256) {
                int c = t & 31, kw = (t >> 5) % pn, i = (t >> 5) / pn;
                float acc = 0.0f;
                for (int k = 0; k < pn; k++)
                    acc = fmaf(sm->wu[k * 16 + i], sm->zbuf[(k * pn + kw) * 32 + c], acc);
                tmpf[t] = acc;   // layout (i*pn + kw)*32 + c
            }
            __syncthreads();
            // pass 2: contract input-w, then update fhat/frest
            for (int t = tid; t < 8192; t += 256) {
                int c = t & 31, j = (t >> 5) & 15, i = t >> 9;
                float acc = 0.0f;
                for (int k = 0; k < pn; k++)
                    acc = fmaf(sm->wu[k * 16 + j], tmpf[(i * pn + k) * 32 + c], acc);
                sm->fhat[t] = __fadd_rn(sm->fhat[t], acc);
                sm->frest[t] = __fsub_rn(sm->frest[t], acc);
            }
        }

        cluster_sync_();   // peer done with g_key before next-scale overwrite
        __syncthreads();
    }

    // ---------- write output: BHWC -> BCHW, split channels by rank ----------
    for (int t = tid; t < 4096; t += 256) {
        int c = rank * 16 + (t >> 8);
        int ij = t & 255;
        out[(b * 32 + c) * 256 + ij] = sm->fhat[ij * 32 + c];
    }
}

// ---------------------------------------------------------------------------
extern "C" void kernel_launch(void* const* d_in, const int* in_sizes, int n_in,
                              void* d_out, int out_size) {
    (void)in_sizes; (void)n_in; (void)out_size;
    const float* f = (const float*)d_in[0];     // [64,32,16,16] f32
    const float* emb = (const float*)d_in[1];   // [4096,32] f32
    float* out = (float*)d_out;                 // [64,32,16,16] f32

    static int smem_set = 0;
    if (!smem_set) {
        cudaFuncSetAttribute(vq_main_kernel,
                             cudaFuncAttributeMaxDynamicSharedMemorySize,
                             (int)sizeof(SMem));
        smem_set = 1;
    }

    vq_prep_kernel<<<16, 256>>>(emb);
    vq_main_kernel<<<128, 256, sizeof(SMem)>>>(f, emb, out);
}